// round 1
// baseline (speedup 1.0000x reference)
#include <cuda_runtime.h>

#define N_NODES   50000
#define N_EDGES   800000
#define F_IN      16
#define F_EDGE    8
#define H         8
#define NUM_GRAPHS 512
// Q row: 64 floats of ea-conditioned precompute + 8 floats of bias term (x@Be)
#define QSTRIDE   72

// Scratch (no allocations allowed) — reused across both layers.
__device__ __align__(16) float g_Q[N_NODES * QSTRIDE];     // 14.4 MB
__device__ __align__(16) float g_agg1[N_NODES * H];        // 1.6 MB
__device__ __align__(16) float g_agg2[N_NODES * H];        // 1.6 MB

// ---------------------------------------------------------------------------
// Layer-1 node precompute: Q[n][f*8+o] = sum_i x[n,i]*We1[f, i*8+o]
//                          Q[n][64+o]  = sum_i x[n,i]*be1[i*8+o]
//                          agg1[n][o]  = x[n]@root1 + b1   (scatter target init)
// 8 lanes per node.
// ---------------------------------------------------------------------------
__global__ void node1_kernel(const float* __restrict__ x,
                             const float* __restrict__ We1,
                             const float* __restrict__ be1,
                             const float* __restrict__ root1,
                             const float* __restrict__ b1) {
    __shared__ float sW[F_EDGE * F_IN * H];  // 1024
    __shared__ float sR[F_IN * H];           // 128
    __shared__ float sB[F_IN * H];           // 128
    __shared__ float sb[H];
    for (int i = threadIdx.x; i < F_EDGE * F_IN * H; i += blockDim.x) sW[i] = We1[i];
    for (int i = threadIdx.x; i < F_IN * H; i += blockDim.x) { sR[i] = root1[i]; sB[i] = be1[i]; }
    if (threadIdx.x < H) sb[threadIdx.x] = b1[threadIdx.x];
    __syncthreads();

    int gid = blockIdx.x * blockDim.x + threadIdx.x;
    int n = gid >> 3, j = gid & 7;
    if (n >= N_NODES) return;

    float xv[F_IN];
    const float4* xp = (const float4*)(x + n * F_IN);
    #pragma unroll
    for (int v = 0; v < 4; v++) {
        float4 t = xp[v];
        xv[v * 4 + 0] = t.x; xv[v * 4 + 1] = t.y; xv[v * 4 + 2] = t.z; xv[v * 4 + 3] = t.w;
    }

    float q[8];
    #pragma unroll
    for (int o = 0; o < 8; o++) {
        float s = 0.f;
        #pragma unroll
        for (int i = 0; i < F_IN; i++) s = fmaf(xv[i], sW[j * 128 + i * 8 + o], s);
        q[o] = s;
    }
    float4* qp = (float4*)(g_Q + n * QSTRIDE + j * 8);
    qp[0] = make_float4(q[0], q[1], q[2], q[3]);
    qp[1] = make_float4(q[4], q[5], q[6], q[7]);

    float qb = 0.f, r = sb[j];
    #pragma unroll
    for (int i = 0; i < F_IN; i++) {
        qb = fmaf(xv[i], sB[i * 8 + j], qb);
        r  = fmaf(xv[i], sR[i * 8 + j], r);
    }
    g_Q[n * QSTRIDE + 64 + j] = qb;
    g_agg1[n * 8 + j] = r;
}

// ---------------------------------------------------------------------------
// Layer-2 node precompute: h = relu(agg1); same structure with We2/be2/root2/b2
// ---------------------------------------------------------------------------
__global__ void node2_kernel(const float* __restrict__ We2,
                             const float* __restrict__ be2,
                             const float* __restrict__ root2,
                             const float* __restrict__ b2) {
    __shared__ float sW[F_EDGE * H * H];  // 512
    __shared__ float sR[H * H];           // 64
    __shared__ float sB[H * H];           // 64
    __shared__ float sb[H];
    for (int i = threadIdx.x; i < F_EDGE * H * H; i += blockDim.x) sW[i] = We2[i];
    for (int i = threadIdx.x; i < H * H; i += blockDim.x) { sR[i] = root2[i]; sB[i] = be2[i]; }
    if (threadIdx.x < H) sb[threadIdx.x] = b2[threadIdx.x];
    __syncthreads();

    int gid = blockIdx.x * blockDim.x + threadIdx.x;
    int n = gid >> 3, j = gid & 7;
    if (n >= N_NODES) return;

    float h[H];
    const float4* hp = (const float4*)(g_agg1 + n * 8);
    float4 a0 = hp[0], a1 = hp[1];
    h[0] = fmaxf(a0.x, 0.f); h[1] = fmaxf(a0.y, 0.f);
    h[2] = fmaxf(a0.z, 0.f); h[3] = fmaxf(a0.w, 0.f);
    h[4] = fmaxf(a1.x, 0.f); h[5] = fmaxf(a1.y, 0.f);
    h[6] = fmaxf(a1.z, 0.f); h[7] = fmaxf(a1.w, 0.f);

    float q[8];
    #pragma unroll
    for (int o = 0; o < 8; o++) {
        float s = 0.f;
        #pragma unroll
        for (int i = 0; i < H; i++) s = fmaf(h[i], sW[j * 64 + i * 8 + o], s);
        q[o] = s;
    }
    float4* qp = (float4*)(g_Q + n * QSTRIDE + j * 8);
    qp[0] = make_float4(q[0], q[1], q[2], q[3]);
    qp[1] = make_float4(q[4], q[5], q[6], q[7]);

    float qb = 0.f, r = sb[j];
    #pragma unroll
    for (int i = 0; i < H; i++) {
        qb = fmaf(h[i], sB[i * 8 + j], qb);
        r  = fmaf(h[i], sR[i * 8 + j], r);
    }
    g_Q[n * QSTRIDE + 64 + j] = qb;
    g_agg2[n * 8 + j] = r;
}

// ---------------------------------------------------------------------------
// Edge pass (used for both layers; layer flag picks the agg buffer).
// 8 lanes per edge. Lane j:
//   - loads ea[e, j] and Q[src][j*8 .. j*8+7]   (coalesced 256B group read)
//   - partial m[o] = ea[j]*Q[src][j*8+o]
//   - 3-round butterfly over the 8-lane group -> full sums in every lane
//   - atomicAdd(agg[dst*8 + j], m[j] + Qbias[src][j])
// ---------------------------------------------------------------------------
__global__ void edge_kernel(const int* __restrict__ ei,
                            const float* __restrict__ ea,
                            int layer) {
    int gid = blockIdx.x * blockDim.x + threadIdx.x;
    int e = gid >> 3, j = gid & 7;
    if (e >= N_EDGES) return;   // grid is exact; guard never taken

    int s = __ldg(&ei[e]);
    int d = __ldg(&ei[N_EDGES + e]);
    float a = __ldg(&ea[gid]);   // ea[e*8 + j] == ea[gid]

    const float4* qp = (const float4*)(g_Q + s * QSTRIDE + j * 8);
    float4 q0 = __ldg(qp);
    float4 q1 = __ldg(qp + 1);

    float m0 = a * q0.x, m1 = a * q0.y, m2 = a * q0.z, m3 = a * q0.w;
    float m4 = a * q1.x, m5 = a * q1.y, m6 = a * q1.z, m7 = a * q1.w;

    #pragma unroll
    for (int off = 4; off >= 1; off >>= 1) {
        m0 += __shfl_xor_sync(0xffffffffu, m0, off, 32);
        m1 += __shfl_xor_sync(0xffffffffu, m1, off, 32);
        m2 += __shfl_xor_sync(0xffffffffu, m2, off, 32);
        m3 += __shfl_xor_sync(0xffffffffu, m3, off, 32);
        m4 += __shfl_xor_sync(0xffffffffu, m4, off, 32);
        m5 += __shfl_xor_sync(0xffffffffu, m5, off, 32);
        m6 += __shfl_xor_sync(0xffffffffu, m6, off, 32);
        m7 += __shfl_xor_sync(0xffffffffu, m7, off, 32);
    }

    float r = m0;
    if (j == 1) r = m1;
    if (j == 2) r = m2;
    if (j == 3) r = m3;
    if (j == 4) r = m4;
    if (j == 5) r = m5;
    if (j == 6) r = m6;
    if (j == 7) r = m7;

    float qb = __ldg(&g_Q[s * QSTRIDE + 64 + j]);
    float* agg = layer ? g_agg2 : g_agg1;
    atomicAdd(&agg[d * 8 + j], r + qb);
}

// ---------------------------------------------------------------------------
// Output init + fused relu / pool / readout
// ---------------------------------------------------------------------------
__global__ void out_init_kernel(const float* __restrict__ blast, float* __restrict__ out) {
    int g = blockIdx.x * blockDim.x + threadIdx.x;
    if (g < NUM_GRAPHS) out[g] = blast[0];
}

__global__ void final_kernel(const int* __restrict__ batch,
                             const float* __restrict__ Wlast,
                             float* __restrict__ out) {
    int n = blockIdx.x * blockDim.x + threadIdx.x;
    if (n >= N_NODES) return;
    const float4* ap = (const float4*)(g_agg2 + n * 8);
    float4 a0 = ap[0], a1 = ap[1];
    float v = 0.f;
    v = fmaf(fmaxf(a0.x, 0.f), __ldg(&Wlast[0]), v);
    v = fmaf(fmaxf(a0.y, 0.f), __ldg(&Wlast[1]), v);
    v = fmaf(fmaxf(a0.z, 0.f), __ldg(&Wlast[2]), v);
    v = fmaf(fmaxf(a0.w, 0.f), __ldg(&Wlast[3]), v);
    v = fmaf(fmaxf(a1.x, 0.f), __ldg(&Wlast[4]), v);
    v = fmaf(fmaxf(a1.y, 0.f), __ldg(&Wlast[5]), v);
    v = fmaf(fmaxf(a1.z, 0.f), __ldg(&Wlast[6]), v);
    v = fmaf(fmaxf(a1.w, 0.f), __ldg(&Wlast[7]), v);
    atomicAdd(&out[__ldg(&batch[n])], v);
}

// ---------------------------------------------------------------------------
extern "C" void kernel_launch(void* const* d_in, const int* in_sizes, int n_in,
                              void* d_out, int out_size) {
    const float* x     = (const float*)d_in[0];
    const int*   ei    = (const int*)  d_in[1];
    const float* ea    = (const float*)d_in[2];
    const int*   batch = (const int*)  d_in[3];
    const float* We1   = (const float*)d_in[4];
    const float* be1   = (const float*)d_in[5];
    const float* root1 = (const float*)d_in[6];
    const float* b1    = (const float*)d_in[7];
    const float* We2   = (const float*)d_in[8];
    const float* be2   = (const float*)d_in[9];
    const float* root2 = (const float*)d_in[10];
    const float* b2    = (const float*)d_in[11];
    const float* Wlast = (const float*)d_in[12];
    const float* blast = (const float*)d_in[13];
    float* out = (float*)d_out;

    const int TPB = 256;
    int node_blocks = (N_NODES * 8 + TPB - 1) / TPB;
    int edge_blocks = (N_EDGES * 8) / TPB;          // 25000, exact
    int fin_blocks  = (N_NODES + TPB - 1) / TPB;

    node1_kernel<<<node_blocks, TPB>>>(x, We1, be1, root1, b1);
    edge_kernel<<<edge_blocks, TPB>>>(ei, ea, 0);
    node2_kernel<<<node_blocks, TPB>>>(We2, be2, root2, b2);
    edge_kernel<<<edge_blocks, TPB>>>(ei, ea, 1);
    out_init_kernel<<<(NUM_GRAPHS + TPB - 1) / TPB, TPB>>>(blast, out);
    final_kernel<<<fin_blocks, TPB>>>(batch, Wlast, out);
}

// round 2
// speedup vs baseline: 2.0665x; 2.0665x over previous
#include <cuda_runtime.h>

#define N_NODES   50000
#define N_EDGES   800000
#define F_IN      16
#define F_EDGE    8
#define H         8
#define NUM_GRAPHS 512
// Q row (o-major): 64 floats Q[o*8+f] + 8 floats of bias term (x@Be)
#define QSTRIDE   72

__device__ __align__(16) float g_Q[N_NODES * QSTRIDE];     // 14.4 MB
__device__ __align__(16) float g_agg1[N_NODES * H];        // 1.6 MB
__device__ __align__(16) float g_agg2[N_NODES * H];        // 1.6 MB

// ---------------------------------------------------------------------------
// Layer-1 node precompute (8 lanes per node, lane j = output channel j):
//   Q[n][j*8+f] = sum_i x[n,i]*We1[f, i*8+j]     (o-major!)
//   Q[n][64+j]  = sum_i x[n,i]*be1[i*8+j]
//   agg1[n][j]  = x[n]@root1[:,j] + b1[j]
// ---------------------------------------------------------------------------
__global__ void node1_kernel(const float* __restrict__ x,
                             const float* __restrict__ We1,
                             const float* __restrict__ be1,
                             const float* __restrict__ root1,
                             const float* __restrict__ b1) {
    __shared__ float sW[F_EDGE * F_IN * H];  // 1024
    __shared__ float sR[F_IN * H];           // 128
    __shared__ float sB[F_IN * H];           // 128
    __shared__ float sb[H];
    for (int i = threadIdx.x; i < F_EDGE * F_IN * H; i += blockDim.x) sW[i] = We1[i];
    for (int i = threadIdx.x; i < F_IN * H; i += blockDim.x) { sR[i] = root1[i]; sB[i] = be1[i]; }
    if (threadIdx.x < H) sb[threadIdx.x] = b1[threadIdx.x];
    __syncthreads();

    int gid = blockIdx.x * blockDim.x + threadIdx.x;
    int n = gid >> 3, j = gid & 7;
    if (n >= N_NODES) return;

    float xv[F_IN];
    const float4* xp = (const float4*)(x + n * F_IN);
    #pragma unroll
    for (int v = 0; v < 4; v++) {
        float4 t = xp[v];
        xv[v * 4 + 0] = t.x; xv[v * 4 + 1] = t.y; xv[v * 4 + 2] = t.z; xv[v * 4 + 3] = t.w;
    }

    // q[f] = x[n] dot We1[f, :, j]
    float q[8];
    #pragma unroll
    for (int f = 0; f < 8; f++) {
        float s = 0.f;
        #pragma unroll
        for (int i = 0; i < F_IN; i++) s = fmaf(xv[i], sW[f * 128 + i * 8 + j], s);
        q[f] = s;
    }
    float4* qp = (float4*)(g_Q + n * QSTRIDE + j * 8);
    qp[0] = make_float4(q[0], q[1], q[2], q[3]);
    qp[1] = make_float4(q[4], q[5], q[6], q[7]);

    float qb = 0.f, r = sb[j];
    #pragma unroll
    for (int i = 0; i < F_IN; i++) {
        qb = fmaf(xv[i], sB[i * 8 + j], qb);
        r  = fmaf(xv[i], sR[i * 8 + j], r);
    }
    g_Q[n * QSTRIDE + 64 + j] = qb;
    g_agg1[n * 8 + j] = r;
}

// ---------------------------------------------------------------------------
// Layer-2 node precompute: h = relu(agg1); same structure (o-major Q)
// ---------------------------------------------------------------------------
__global__ void node2_kernel(const float* __restrict__ We2,
                             const float* __restrict__ be2,
                             const float* __restrict__ root2,
                             const float* __restrict__ b2) {
    __shared__ float sW[F_EDGE * H * H];  // 512
    __shared__ float sR[H * H];           // 64
    __shared__ float sB[H * H];           // 64
    __shared__ float sb[H];
    for (int i = threadIdx.x; i < F_EDGE * H * H; i += blockDim.x) sW[i] = We2[i];
    for (int i = threadIdx.x; i < H * H; i += blockDim.x) { sR[i] = root2[i]; sB[i] = be2[i]; }
    if (threadIdx.x < H) sb[threadIdx.x] = b2[threadIdx.x];
    __syncthreads();

    int gid = blockIdx.x * blockDim.x + threadIdx.x;
    int n = gid >> 3, j = gid & 7;
    if (n >= N_NODES) return;

    float h[H];
    const float4* hp = (const float4*)(g_agg1 + n * 8);
    float4 a0 = hp[0], a1 = hp[1];
    h[0] = fmaxf(a0.x, 0.f); h[1] = fmaxf(a0.y, 0.f);
    h[2] = fmaxf(a0.z, 0.f); h[3] = fmaxf(a0.w, 0.f);
    h[4] = fmaxf(a1.x, 0.f); h[5] = fmaxf(a1.y, 0.f);
    h[6] = fmaxf(a1.z, 0.f); h[7] = fmaxf(a1.w, 0.f);

    float q[8];
    #pragma unroll
    for (int f = 0; f < 8; f++) {
        float s = 0.f;
        #pragma unroll
        for (int i = 0; i < H; i++) s = fmaf(h[i], sW[f * 64 + i * 8 + j], s);
        q[f] = s;
    }
    float4* qp = (float4*)(g_Q + n * QSTRIDE + j * 8);
    qp[0] = make_float4(q[0], q[1], q[2], q[3]);
    qp[1] = make_float4(q[4], q[5], q[6], q[7]);

    float qb = 0.f, r = sb[j];
    #pragma unroll
    for (int i = 0; i < H; i++) {
        qb = fmaf(h[i], sB[i * 8 + j], qb);
        r  = fmaf(h[i], sR[i * 8 + j], r);
    }
    g_Q[n * QSTRIDE + 64 + j] = qb;
    g_agg2[n * 8 + j] = r;
}

// ---------------------------------------------------------------------------
// Edge pass: 8 lanes per edge, 2 edges per thread (ILP), NO shuffles.
// Lane j: r = sum_f ea[e,f] * Q[src][j*8+f]  + Qbias[src][j]
//         atomicAdd(agg[dst*8 + j], r)
// ea loads are group-uniform (broadcast); Q loads coalesced 256B per group.
// ---------------------------------------------------------------------------
#define EPT 2
#define HALF_E (N_EDGES / EPT)

__global__ void __launch_bounds__(256) edge_kernel(const int* __restrict__ ei,
                                                   const float* __restrict__ ea,
                                                   int layer) {
    int gid = blockIdx.x * blockDim.x + threadIdx.x;
    int e0 = gid >> 3, j = gid & 7;
    float* agg = layer ? g_agg2 : g_agg1;

    #pragma unroll
    for (int k = 0; k < EPT; k++) {
        int e = e0 + k * HALF_E;
        int s = __ldg(&ei[e]);
        int d = __ldg(&ei[N_EDGES + e]);

        const float4* eap = (const float4*)(ea + e * 8);
        float4 a0 = __ldg(eap);
        float4 a1 = __ldg(eap + 1);

        const float4* qp = (const float4*)(g_Q + s * QSTRIDE + j * 8);
        float4 q0 = __ldg(qp);
        float4 q1 = __ldg(qp + 1);
        float qb = __ldg(&g_Q[s * QSTRIDE + 64 + j]);

        float r = qb;
        r = fmaf(a0.x, q0.x, r);
        r = fmaf(a0.y, q0.y, r);
        r = fmaf(a0.z, q0.z, r);
        r = fmaf(a0.w, q0.w, r);
        r = fmaf(a1.x, q1.x, r);
        r = fmaf(a1.y, q1.y, r);
        r = fmaf(a1.z, q1.z, r);
        r = fmaf(a1.w, q1.w, r);

        atomicAdd(&agg[d * 8 + j], r);
    }
}

// ---------------------------------------------------------------------------
// Output init + fused relu / pool / readout with warp-aggregated atomics.
// batch is sorted, so most warps are graph-uniform -> 1 atomic per warp.
// ---------------------------------------------------------------------------
__global__ void out_init_kernel(const float* __restrict__ blast, float* __restrict__ out) {
    int g = blockIdx.x * blockDim.x + threadIdx.x;
    if (g < NUM_GRAPHS) out[g] = blast[0];
}

__global__ void final_kernel(const int* __restrict__ batch,
                             const float* __restrict__ Wlast,
                             float* __restrict__ out) {
    int n = blockIdx.x * blockDim.x + threadIdx.x;
    bool valid = (n < N_NODES);
    int nc = valid ? n : (N_NODES - 1);

    const float4* ap = (const float4*)(g_agg2 + nc * 8);
    float4 a0 = ap[0], a1 = ap[1];
    float v = 0.f;
    v = fmaf(fmaxf(a0.x, 0.f), __ldg(&Wlast[0]), v);
    v = fmaf(fmaxf(a0.y, 0.f), __ldg(&Wlast[1]), v);
    v = fmaf(fmaxf(a0.z, 0.f), __ldg(&Wlast[2]), v);
    v = fmaf(fmaxf(a0.w, 0.f), __ldg(&Wlast[3]), v);
    v = fmaf(fmaxf(a1.x, 0.f), __ldg(&Wlast[4]), v);
    v = fmaf(fmaxf(a1.y, 0.f), __ldg(&Wlast[5]), v);
    v = fmaf(fmaxf(a1.z, 0.f), __ldg(&Wlast[6]), v);
    v = fmaf(fmaxf(a1.w, 0.f), __ldg(&Wlast[7]), v);
    if (!valid) v = 0.f;

    int b = __ldg(&batch[nc]);
    int b0 = __shfl_sync(0xffffffffu, b, 0);
    if (__all_sync(0xffffffffu, b == b0)) {
        // warp-uniform graph: tree-reduce, single atomic
        #pragma unroll
        for (int off = 16; off >= 1; off >>= 1)
            v += __shfl_xor_sync(0xffffffffu, v, off, 32);
        if ((threadIdx.x & 31) == 0) atomicAdd(&out[b0], v);
    } else {
        if (valid) atomicAdd(&out[b], v);
    }
}

// ---------------------------------------------------------------------------
extern "C" void kernel_launch(void* const* d_in, const int* in_sizes, int n_in,
                              void* d_out, int out_size) {
    const float* x     = (const float*)d_in[0];
    const int*   ei    = (const int*)  d_in[1];
    const float* ea    = (const float*)d_in[2];
    const int*   batch = (const int*)  d_in[3];
    const float* We1   = (const float*)d_in[4];
    const float* be1   = (const float*)d_in[5];
    const float* root1 = (const float*)d_in[6];
    const float* b1    = (const float*)d_in[7];
    const float* We2   = (const float*)d_in[8];
    const float* be2   = (const float*)d_in[9];
    const float* root2 = (const float*)d_in[10];
    const float* b2    = (const float*)d_in[11];
    const float* Wlast = (const float*)d_in[12];
    const float* blast = (const float*)d_in[13];
    float* out = (float*)d_out;

    const int TPB = 256;
    int node_blocks = (N_NODES * 8 + TPB - 1) / TPB;
    int edge_blocks = (HALF_E * 8) / TPB;           // 12500, exact
    int fin_blocks  = (N_NODES + TPB - 1) / TPB;

    node1_kernel<<<node_blocks, TPB>>>(x, We1, be1, root1, b1);
    edge_kernel<<<edge_blocks, TPB>>>(ei, ea, 0);
    node2_kernel<<<node_blocks, TPB>>>(We2, be2, root2, b2);
    edge_kernel<<<edge_blocks, TPB>>>(ei, ea, 1);
    out_init_kernel<<<(NUM_GRAPHS + TPB - 1) / TPB, TPB>>>(blast, out);
    final_kernel<<<fin_blocks, TPB>>>(batch, Wlast, out);
}